// round 1
// baseline (speedup 1.0000x reference)
#include <cuda_runtime.h>
#include <math.h>

#define D_MODEL 256
#define NH 8
#define NL 4
#define NP 4
#define DHEAD 32
#define BATCH 2
#define MAX_M 40960   // >= BATCH * Lq = 39894

// Scratch (static device globals -- no allocation at runtime)
__device__ float g_value[(size_t)MAX_M * D_MODEL];   // (N,H,Lv,Dh)
__device__ float g_off  [(size_t)MAX_M * D_MODEL];   // (N,Lq,H,L,P,2)
__device__ float g_attn [(size_t)MAX_M * (NH*NL*NP)];// logits (N,Lq,H,16)
__device__ float g_acc  [(size_t)MAX_M * D_MODEL];   // (N,Lq,H,Dh)

// ---------------------------------------------------------------------------
// SGEMM: C[M,N] = A[M,K] @ W[N,K]^T + bias[N]
// EPI==0: plain row-major store.  EPI==1: remap to value layout (N,H,Lv,Dh).
// ---------------------------------------------------------------------------
#define BM 128
#define BN 128
#define BKK 8

template<int EPI>
__global__ __launch_bounds__(256, 2)
void sgemm_nt(const float* __restrict__ A, const float* __restrict__ W,
              const float* __restrict__ bias, float* __restrict__ C,
              int M, int N, int K, int Lv)
{
    __shared__ float As[BKK][BM];
    __shared__ float Ws[BKK][BN];

    const int tid  = threadIdx.x;
    const int tx   = tid & 15;        // 16 cols of threads
    const int ty   = tid >> 4;        // 16 rows of threads
    const int brow = blockIdx.x * BM;
    const int bcol = blockIdx.y * BN;

    float acc[8][8];
#pragma unroll
    for (int i = 0; i < 8; i++)
#pragma unroll
        for (int j = 0; j < 8; j++) acc[i][j] = 0.f;

    const int ldRow = tid >> 1;           // 0..127
    const int ldCol = (tid & 1) * 4;      // 0 or 4

    for (int kt = 0; kt < K; kt += BKK) {
        // A tile (guard M edge)
        float4 av;
        int gr = brow + ldRow;
        if (gr < M)
            av = *reinterpret_cast<const float4*>(A + (size_t)gr * K + kt + ldCol);
        else
            av = make_float4(0.f, 0.f, 0.f, 0.f);
        As[ldCol + 0][ldRow] = av.x;
        As[ldCol + 1][ldRow] = av.y;
        As[ldCol + 2][ldRow] = av.z;
        As[ldCol + 3][ldRow] = av.w;

        // W tile (N is a multiple of 128 -> no guard)
        float4 wv = *reinterpret_cast<const float4*>(W + (size_t)(bcol + ldRow) * K + kt + ldCol);
        Ws[ldCol + 0][ldRow] = wv.x;
        Ws[ldCol + 1][ldRow] = wv.y;
        Ws[ldCol + 2][ldRow] = wv.z;
        Ws[ldCol + 3][ldRow] = wv.w;

        __syncthreads();

#pragma unroll
        for (int kk = 0; kk < BKK; kk++) {
            float ra[8], rw[8];
#pragma unroll
            for (int i = 0; i < 8; i++) ra[i] = As[kk][ty * 8 + i];
#pragma unroll
            for (int j = 0; j < 8; j++) rw[j] = Ws[kk][tx * 8 + j];
#pragma unroll
            for (int i = 0; i < 8; i++)
#pragma unroll
                for (int j = 0; j < 8; j++)
                    acc[i][j] = fmaf(ra[i], rw[j], acc[i][j]);
        }
        __syncthreads();
    }

    // Epilogue
#pragma unroll
    for (int i = 0; i < 8; i++) {
        int r = brow + ty * 8 + i;
        if (r >= M) continue;
        int nb = 0, l = 0;
        if (EPI == 1) { nb = r / Lv; l = r - nb * Lv; }
#pragma unroll
        for (int j = 0; j < 8; j++) {
            int c = bcol + tx * 8 + j;
            float val = acc[i][j] + __ldg(bias + c);
            if (EPI == 0) {
                C[(size_t)r * N + c] = val;
            } else {
                int h  = c >> 5;
                int dh = c & 31;
                C[((((size_t)(nb * NH + h)) * Lv) + l) * DHEAD + dh] = val;
            }
        }
    }
}

// ---------------------------------------------------------------------------
// Sampling + softmax: one warp per (n, q, h); lane == channel (Dh = 32).
// x = ref_x*Wl + off_x - 0.5 ;  y = ref_y*Hl + off_y - 0.5   (exact algebra)
// ---------------------------------------------------------------------------
__global__ __launch_bounds__(256)
void msda_sample(const float* __restrict__ ref,
                 const int* __restrict__ shapes,
                 const int* __restrict__ lstart,
                 int Lq)
{
    const int gwarp = (blockIdx.x * blockDim.x + threadIdx.x) >> 5;
    const int lane  = threadIdx.x & 31;
    const int total = BATCH * Lq * NH;
    if (gwarp >= total) return;

    const int h = gwarp & (NH - 1);
    const int q = (gwarp >> 3) % Lq;
    const int n = gwarp / (NH * Lq);
    const size_t m = (size_t)n * Lq + q;

    // sampling offsets: 32 floats per (n,q,h); lane l holds element l
    const float offv = g_off[(m * NH + h) * (NL * NP * 2) + lane];

    // attention softmax over 16 logits (warp-redundant via shuffles)
    float logit = (lane < NL * NP) ? g_attn[(m * NH + h) * (NL * NP) + lane] : -INFINITY;
    float mx = logit;
#pragma unroll
    for (int s = 16; s > 0; s >>= 1) mx = fmaxf(mx, __shfl_xor_sync(0xffffffffu, mx, s));
    float e = (lane < NL * NP) ? __expf(logit - mx) : 0.f;
    float sum = e;
#pragma unroll
    for (int s = 16; s > 0; s >>= 1) sum += __shfl_xor_sync(0xffffffffu, sum, s);
    const float inv = 1.f / sum;

    const size_t rbase = m * (NL * 2);
    const int Lv = Lq;
    float accv = 0.f;

#pragma unroll
    for (int lvl = 0; lvl < NL; lvl++) {
        const int Hl = __ldg(shapes + lvl * 2 + 0);
        const int Wl = __ldg(shapes + lvl * 2 + 1);
        const int st = __ldg(lstart + lvl);
        const float rx = __ldg(ref + rbase + lvl * 2 + 0);
        const float ry = __ldg(ref + rbase + lvl * 2 + 1);
        const float* vb = g_value + ((((size_t)(n * NH + h)) * Lv) + st) * DHEAD;

#pragma unroll
        for (int p = 0; p < NP; p++) {
            const int pt = lvl * NP + p;
            const float ox = __shfl_sync(0xffffffffu, offv, 2 * pt);
            const float oy = __shfl_sync(0xffffffffu, offv, 2 * pt + 1);
            const float aw = __shfl_sync(0xffffffffu, e, pt) * inv;

            const float x = rx * (float)Wl + ox - 0.5f;
            const float y = ry * (float)Hl + oy - 0.5f;
            const float xf = floorf(x), yf = floorf(y);
            const float lx = x - xf, ly = y - yf;
            const int x0 = (int)xf, y0 = (int)yf;
            const int x1 = x0 + 1,  y1 = y0 + 1;

            const bool vx0 = (x0 >= 0) & (x0 < Wl);
            const bool vx1 = (x1 >= 0) & (x1 < Wl);
            const bool vy0 = (y0 >= 0) & (y0 < Hl);
            const bool vy1 = (y1 >= 0) & (y1 < Hl);

            const int x0c = min(max(x0, 0), Wl - 1);
            const int x1c = min(max(x1, 0), Wl - 1);
            const int y0c = min(max(y0, 0), Hl - 1);
            const int y1c = min(max(y1, 0), Hl - 1);

            const float v00 = __ldg(vb + ((size_t)(y0c * Wl + x0c)) * DHEAD + lane);
            const float v10 = __ldg(vb + ((size_t)(y0c * Wl + x1c)) * DHEAD + lane);
            const float v01 = __ldg(vb + ((size_t)(y1c * Wl + x0c)) * DHEAD + lane);
            const float v11 = __ldg(vb + ((size_t)(y1c * Wl + x1c)) * DHEAD + lane);

            const float w00 = (1.f - lx) * (1.f - ly);
            const float w10 = lx * (1.f - ly);
            const float w01 = (1.f - lx) * ly;
            const float w11 = lx * ly;

            float bil = 0.f;
            if (vx0 & vy0) bil += w00 * v00;
            if (vx1 & vy0) bil += w10 * v10;
            if (vx0 & vy1) bil += w01 * v01;
            if (vx1 & vy1) bil += w11 * v11;

            accv += aw * bil;
        }
    }

    g_acc[(m * NH + h) * DHEAD + lane] = accv;
}

// ---------------------------------------------------------------------------
// Launch
// ---------------------------------------------------------------------------
extern "C" void kernel_launch(void* const* d_in, const int* in_sizes, int n_in,
                              void* d_out, int out_size)
{
    const float* query  = (const float*)d_in[0];
    const float* refp   = (const float*)d_in[1];
    const float* xin    = (const float*)d_in[2];
    const int*   shapes = (const int*)  d_in[3];
    const int*   lstart = (const int*)  d_in[4];
    const float* W_samp = (const float*)d_in[5];
    const float* b_samp = (const float*)d_in[6];
    const float* W_attn = (const float*)d_in[7];
    const float* b_attn = (const float*)d_in[8];
    const float* W_val  = (const float*)d_in[9];
    const float* b_val  = (const float*)d_in[10];
    const float* W_out  = (const float*)d_in[11];
    const float* b_out  = (const float*)d_in[12];
    float* out = (float*)d_out;

    const int Lq = in_sizes[0] / (BATCH * D_MODEL);
    const int M  = BATCH * Lq;

    void *pv, *po, *pa, *pc;
    cudaGetSymbolAddress(&pv, g_value);
    cudaGetSymbolAddress(&po, g_off);
    cudaGetSymbolAddress(&pa, g_attn);
    cudaGetSymbolAddress(&pc, g_acc);

    dim3 blk(256);
    dim3 grid256((M + BM - 1) / BM, D_MODEL / BN);       // N = 256
    dim3 grid128((M + BM - 1) / BM, (NH * NL * NP) / BN); // N = 128

    // 1) value projection (+ layout remap to (N,H,Lv,Dh))
    sgemm_nt<1><<<grid256, blk>>>(xin, W_val, b_val, (float*)pv, M, D_MODEL, D_MODEL, Lq);
    // 2) sampling offsets
    sgemm_nt<0><<<grid256, blk>>>(query, W_samp, b_samp, (float*)po, M, D_MODEL, D_MODEL, Lq);
    // 3) attention logits
    sgemm_nt<0><<<grid128, blk>>>(query, W_attn, b_attn, (float*)pa, M, NH * NL * NP, D_MODEL, Lq);
    // 4) softmax + deformable sampling
    {
        const int totalWarps = BATCH * Lq * NH;
        const int nblk = (totalWarps + 7) / 8;   // 8 warps / block
        msda_sample<<<nblk, blk>>>(refp, shapes, lstart, Lq);
    }
    // 5) output projection
    sgemm_nt<0><<<grid256, blk>>>((const float*)pc, W_out, b_out, out, M, D_MODEL, D_MODEL, Lq);
}

// round 2
// speedup vs baseline: 1.2250x; 1.2250x over previous
#include <cuda_runtime.h>
#include <math.h>

#define D_MODEL 256
#define NH 8
#define NL 4
#define NP 4
#define DHEAD 32
#define BATCH 2
#define MAX_M 40960   // >= BATCH * Lq = 39894

// Scratch (static device globals -- no allocation at runtime)
__device__ float g_value[(size_t)MAX_M * D_MODEL];   // (N,H,Lv,Dh)
__device__ float g_off  [(size_t)MAX_M * D_MODEL];   // (N,Lq,H,L,P,2)
__device__ float g_attn [(size_t)MAX_M * (NH*NL*NP)];// logits (N,Lq,H,16)
__device__ float g_acc  [(size_t)MAX_M * D_MODEL];   // (N,Lq,H,Dh)

// ---------------------------------------------------------------------------
// SGEMM: C[M,N] = A[M,K] @ W[N,K]^T + bias[N]
// 128x128 tile, BK=16, register-prefetch + double-buffered smem (1 sync/iter)
// EPI==0: plain row-major store.  EPI==1: remap to value layout (N,H,Lv,Dh).
// ---------------------------------------------------------------------------
#define BM 128
#define BN 128
#define BKK 16

template<int EPI>
__global__ __launch_bounds__(256)
void sgemm_nt(const float* __restrict__ A, const float* __restrict__ W,
              const float* __restrict__ bias, float* __restrict__ C,
              int M, int N, int K, int Lv)
{
    __shared__ float As[2][BKK][BM];
    __shared__ float Ws[2][BKK][BN];

    const int tid  = threadIdx.x;
    const int tx   = tid & 15;        // 16 cols of threads
    const int ty   = tid >> 4;        // 16 rows of threads
    const int brow = blockIdx.x * BM;
    const int bcol = blockIdx.y * BN;

    const int lrow = tid >> 2;            // 0..63
    const int lc   = (tid & 3) * 4;       // 0,4,8,12

    float4 pa[2], pw[2];

    // prefetch tile 0
    {
        int kt = 0;
#pragma unroll
        for (int i = 0; i < 2; i++) {
            int gr = brow + lrow + i * 64;
            pa[i] = (gr < M) ? *reinterpret_cast<const float4*>(A + (size_t)gr * K + kt + lc)
                             : make_float4(0.f, 0.f, 0.f, 0.f);
            pw[i] = *reinterpret_cast<const float4*>(W + (size_t)(bcol + lrow + i * 64) * K + kt + lc);
        }
#pragma unroll
        for (int i = 0; i < 2; i++) {
            int row = lrow + i * 64;
            As[0][lc + 0][row] = pa[i].x; As[0][lc + 1][row] = pa[i].y;
            As[0][lc + 2][row] = pa[i].z; As[0][lc + 3][row] = pa[i].w;
            Ws[0][lc + 0][row] = pw[i].x; Ws[0][lc + 1][row] = pw[i].y;
            Ws[0][lc + 2][row] = pw[i].z; Ws[0][lc + 3][row] = pw[i].w;
        }
    }
    __syncthreads();

    float acc[8][8];
#pragma unroll
    for (int i = 0; i < 8; i++)
#pragma unroll
        for (int j = 0; j < 8; j++) acc[i][j] = 0.f;

    const int nk = K / BKK;
    for (int t = 0; t < nk; t++) {
        const int cur = t & 1;
        if (t + 1 < nk) {
            int kt = (t + 1) * BKK;
#pragma unroll
            for (int i = 0; i < 2; i++) {
                int gr = brow + lrow + i * 64;
                pa[i] = (gr < M) ? *reinterpret_cast<const float4*>(A + (size_t)gr * K + kt + lc)
                                 : make_float4(0.f, 0.f, 0.f, 0.f);
                pw[i] = *reinterpret_cast<const float4*>(W + (size_t)(bcol + lrow + i * 64) * K + kt + lc);
            }
        }

#pragma unroll
        for (int kk = 0; kk < BKK; kk++) {
            float4 a0 = *reinterpret_cast<const float4*>(&As[cur][kk][ty * 8]);
            float4 a1 = *reinterpret_cast<const float4*>(&As[cur][kk][ty * 8 + 4]);
            float4 w0 = *reinterpret_cast<const float4*>(&Ws[cur][kk][tx * 8]);
            float4 w1 = *reinterpret_cast<const float4*>(&Ws[cur][kk][tx * 8 + 4]);
            float ra[8] = {a0.x, a0.y, a0.z, a0.w, a1.x, a1.y, a1.z, a1.w};
            float rw[8] = {w0.x, w0.y, w0.z, w0.w, w1.x, w1.y, w1.z, w1.w};
#pragma unroll
            for (int i = 0; i < 8; i++)
#pragma unroll
                for (int j = 0; j < 8; j++)
                    acc[i][j] = fmaf(ra[i], rw[j], acc[i][j]);
        }

        if (t + 1 < nk) {
            const int nxt = cur ^ 1;
#pragma unroll
            for (int i = 0; i < 2; i++) {
                int row = lrow + i * 64;
                As[nxt][lc + 0][row] = pa[i].x; As[nxt][lc + 1][row] = pa[i].y;
                As[nxt][lc + 2][row] = pa[i].z; As[nxt][lc + 3][row] = pa[i].w;
                Ws[nxt][lc + 0][row] = pw[i].x; Ws[nxt][lc + 1][row] = pw[i].y;
                Ws[nxt][lc + 2][row] = pw[i].z; Ws[nxt][lc + 3][row] = pw[i].w;
            }
        }
        __syncthreads();
    }

    // Epilogue
#pragma unroll
    for (int i = 0; i < 8; i++) {
        int r = brow + ty * 8 + i;
        if (r >= M) continue;
        int nb = 0, l = 0;
        if (EPI == 1) { nb = r / Lv; l = r - nb * Lv; }
#pragma unroll
        for (int j = 0; j < 8; j++) {
            int c = bcol + tx * 8 + j;
            float val = acc[i][j] + __ldg(bias + c);
            if (EPI == 0) {
                C[(size_t)r * N + c] = val;
            } else {
                int h  = c >> 5;
                int dh = c & 31;
                C[((((size_t)(nb * NH + h)) * Lv) + l) * DHEAD + dh] = val;
            }
        }
    }
}

// ---------------------------------------------------------------------------
// Sampling + softmax, two-phase.
// Block = 256 threads, 16 units (n,q,h) per block.
// Phase 1: thread (u,pt) computes softmax weight + 4 corner offsets/weights.
// Phase 2: 8 warps x 2 units, lane = channel; gather + fma only.
// ---------------------------------------------------------------------------
__global__ __launch_bounds__(256)
void msda_sample(const float* __restrict__ ref,
                 const int* __restrict__ shapes,
                 const int* __restrict__ lstart,
                 int Lq, int total)
{
    __shared__ int   s_idx[16][16][4];
    __shared__ float s_w  [16][16][4];
    __shared__ int   s_vbase[16];

    const int tid = threadIdx.x;

    // ---------------- Phase 1 ----------------
    {
        const int u  = tid >> 4;
        const int pt = tid & 15;
        const int gu = blockIdx.x * 16 + u;
        const bool act = gu < total;

        const int h  = gu & (NH - 1);
        const int mq = gu >> 3;                    // n*Lq + q

        // softmax over the unit's 16 logits (16-lane xor reduction)
        float logit = act ? __ldg(g_attn + (size_t)gu * 16 + pt) : 0.f;
        float mx = logit;
#pragma unroll
        for (int s = 8; s > 0; s >>= 1) mx = fmaxf(mx, __shfl_xor_sync(0xffffffffu, mx, s));
        float e = __expf(logit - mx);
        float sum = e;
#pragma unroll
        for (int s = 8; s > 0; s >>= 1) sum += __shfl_xor_sync(0xffffffffu, sum, s);
        const float aw = e / sum;

        if (act) {
            const int lvl = pt >> 2;
            const int Hl = __ldg(shapes + lvl * 2 + 0);
            const int Wl = __ldg(shapes + lvl * 2 + 1);
            const int st = __ldg(lstart + lvl);

            const float rx = __ldg(ref + (size_t)mq * (NL * 2) + lvl * 2 + 0);
            const float ry = __ldg(ref + (size_t)mq * (NL * 2) + lvl * 2 + 1);
            const float ox = __ldg(g_off + (size_t)gu * 32 + 2 * pt + 0);
            const float oy = __ldg(g_off + (size_t)gu * 32 + 2 * pt + 1);

            const float x = fmaf(rx, (float)Wl, ox) - 0.5f;
            const float y = fmaf(ry, (float)Hl, oy) - 0.5f;
            const float xf = floorf(x), yf = floorf(y);
            const float lx = x - xf, ly = y - yf;
            const int x0 = (int)xf, y0 = (int)yf;
            const int x1 = x0 + 1,  y1 = y0 + 1;

            const float vx0 = (x0 >= 0 && x0 < Wl) ? 1.f : 0.f;
            const float vx1 = (x1 >= 0 && x1 < Wl) ? 1.f : 0.f;
            const float vy0 = (y0 >= 0 && y0 < Hl) ? 1.f : 0.f;
            const float vy1 = (y1 >= 0 && y1 < Hl) ? 1.f : 0.f;

            const int x0c = min(max(x0, 0), Wl - 1);
            const int x1c = min(max(x1, 0), Wl - 1);
            const int y0c = min(max(y0, 0), Hl - 1);
            const int y1c = min(max(y1, 0), Hl - 1);

            const int r0 = (st + y0c * Wl) * DHEAD;
            const int r1 = (st + y1c * Wl) * DHEAD;
            s_idx[u][pt][0] = r0 + x0c * DHEAD;
            s_idx[u][pt][1] = r0 + x1c * DHEAD;
            s_idx[u][pt][2] = r1 + x0c * DHEAD;
            s_idx[u][pt][3] = r1 + x1c * DHEAD;

            s_w[u][pt][0] = aw * (1.f - lx) * (1.f - ly) * vx0 * vy0;
            s_w[u][pt][1] = aw * lx * (1.f - ly) * vx1 * vy0;
            s_w[u][pt][2] = aw * (1.f - lx) * ly * vx0 * vy1;
            s_w[u][pt][3] = aw * lx * ly * vx1 * vy1;

            if (pt == 0) {
                const int n = mq / Lq;
                s_vbase[u] = ((n * NH + h) * Lq) * DHEAD;
            }
        }
    }
    __syncthreads();

    // ---------------- Phase 2 ----------------
    {
        const int warp = tid >> 5;
        const int lane = tid & 31;
#pragma unroll
        for (int uu = 0; uu < 2; uu++) {
            const int u  = warp * 2 + uu;
            const int gu = blockIdx.x * 16 + u;
            if (gu >= total) continue;

            const float* bp = g_value + s_vbase[u] + lane;
            float acc = 0.f;
#pragma unroll
            for (int pt = 0; pt < 16; pt++) {
                const int4   id = *reinterpret_cast<const int4*>(s_idx[u][pt]);
                const float4 w  = *reinterpret_cast<const float4*>(s_w[u][pt]);
                acc = fmaf(w.x, __ldg(bp + id.x), acc);
                acc = fmaf(w.y, __ldg(bp + id.y), acc);
                acc = fmaf(w.z, __ldg(bp + id.z), acc);
                acc = fmaf(w.w, __ldg(bp + id.w), acc);
            }
            g_acc[(size_t)gu * DHEAD + lane] = acc;
        }
    }
}

// ---------------------------------------------------------------------------
// Launch
// ---------------------------------------------------------------------------
extern "C" void kernel_launch(void* const* d_in, const int* in_sizes, int n_in,
                              void* d_out, int out_size)
{
    const float* query  = (const float*)d_in[0];
    const float* refp   = (const float*)d_in[1];
    const float* xin    = (const float*)d_in[2];
    const int*   shapes = (const int*)  d_in[3];
    const int*   lstart = (const int*)  d_in[4];
    const float* W_samp = (const float*)d_in[5];
    const float* b_samp = (const float*)d_in[6];
    const float* W_attn = (const float*)d_in[7];
    const float* b_attn = (const float*)d_in[8];
    const float* W_val  = (const float*)d_in[9];
    const float* b_val  = (const float*)d_in[10];
    const float* W_out  = (const float*)d_in[11];
    const float* b_out  = (const float*)d_in[12];
    float* out = (float*)d_out;

    const int Lq = in_sizes[0] / (BATCH * D_MODEL);
    const int M  = BATCH * Lq;

    void *pv, *po, *pa, *pc;
    cudaGetSymbolAddress(&pv, g_value);
    cudaGetSymbolAddress(&po, g_off);
    cudaGetSymbolAddress(&pa, g_attn);
    cudaGetSymbolAddress(&pc, g_acc);

    dim3 blk(256);
    dim3 grid256((M + BM - 1) / BM, D_MODEL / BN);        // N = 256
    dim3 grid128((M + BM - 1) / BM, (NH * NL * NP) / BN); // N = 128

    // 1) value projection (+ layout remap to (N,H,Lv,Dh))
    sgemm_nt<1><<<grid256, blk>>>(xin, W_val, b_val, (float*)pv, M, D_MODEL, D_MODEL, Lq);
    // 2) sampling offsets
    sgemm_nt<0><<<grid256, blk>>>(query, W_samp, b_samp, (float*)po, M, D_MODEL, D_MODEL, Lq);
    // 3) attention logits
    sgemm_nt<0><<<grid128, blk>>>(query, W_attn, b_attn, (float*)pa, M, NH * NL * NP, D_MODEL, Lq);
    // 4) softmax + deformable sampling
    {
        const int total = M * NH;                 // units (n,q,h)
        const int nblk  = (total + 15) / 16;
        msda_sample<<<nblk, blk>>>(refp, shapes, lstart, Lq, total);
    }
    // 5) output projection
    sgemm_nt<0><<<grid256, blk>>>((const float*)pc, W_out, b_out, out, M, D_MODEL, D_MODEL, Lq);
}

// round 3
// speedup vs baseline: 2.5697x; 2.0977x over previous
#include <cuda_runtime.h>
#include <math.h>
#include <stdint.h>

#define D_MODEL 256
#define NH 8
#define NL 4
#define NP 4
#define DHEAD 32
#define BATCH 2
#define MAX_M 40960   // >= BATCH * Lq = 39894

// Scratch (static device globals -- no allocation at runtime)
__device__ float g_value[(size_t)MAX_M * D_MODEL];   // (N,H,Lv,Dh)
__device__ float g_off  [(size_t)MAX_M * D_MODEL];   // (N,Lq,H,L,P,2)
__device__ float g_attn [(size_t)MAX_M * (NH*NL*NP)];// logits (N,Lq,H,16)
__device__ float g_acc  [(size_t)MAX_M * D_MODEL];   // (N,Lq,H,Dh)

// ---------------------------------------------------------------------------
// TF32 tensor-core GEMM: C[M,N] = A[M,K] @ W[N,K]^T + bias[N]
// 128x128x16 block tile, 8 warps x (64x32) warp tile, mma.m16n8k8 tf32.
// EPI==0: plain row-major store.  EPI==1: remap to value layout (N,H,Lv,Dh).
// ---------------------------------------------------------------------------
#define BM 128
#define BN 128
#define BKK 16
#define PAD 8

__device__ __forceinline__ float to_tf32(float x) {
    uint32_t u;
    asm("cvt.rna.tf32.f32 %0, %1;" : "=r"(u) : "f"(x));
    return __uint_as_float(u);
}

__device__ __forceinline__ void mma_tf32(float* c, const uint32_t* a, const uint32_t* b) {
    asm volatile(
        "mma.sync.aligned.m16n8k8.row.col.f32.tf32.tf32.f32 "
        "{%0,%1,%2,%3}, {%4,%5,%6,%7}, {%8,%9}, {%0,%1,%2,%3};"
        : "+f"(c[0]), "+f"(c[1]), "+f"(c[2]), "+f"(c[3])
        : "r"(a[0]), "r"(a[1]), "r"(a[2]), "r"(a[3]), "r"(b[0]), "r"(b[1]));
}

template<int EPI>
__global__ __launch_bounds__(256)
void tgemm_nt(const float* __restrict__ A, const float* __restrict__ W,
              const float* __restrict__ bias, float* __restrict__ C,
              int M, int N, int K, int Lv)
{
    __shared__ float As[2][BKK][BM + PAD];
    __shared__ float Ws[2][BKK][BN + PAD];

    const int tid  = threadIdx.x;
    const int brow = blockIdx.x * BM;
    const int bcol = blockIdx.y * BN;

    const int warp = tid >> 5;
    const int lane = tid & 31;
    const int wm   = (warp & 1) * 64;     // warp M offset (2 warp-rows)
    const int wn   = (warp >> 1) * 32;    // warp N offset (4 warp-cols)
    const int lr   = lane >> 2;           // 0..7
    const int lc   = lane & 3;            // 0..3

    const int ldRow = tid >> 2;           // 0..63
    const int ldCol = (tid & 3) * 4;      // 0,4,8,12

    float4 pa[2], pw[2];

    // prefetch tile 0
    {
#pragma unroll
        for (int i = 0; i < 2; i++) {
            int gr = brow + ldRow + i * 64;
            pa[i] = (gr < M) ? *reinterpret_cast<const float4*>(A + (size_t)gr * K + ldCol)
                             : make_float4(0.f, 0.f, 0.f, 0.f);
            pw[i] = *reinterpret_cast<const float4*>(W + (size_t)(bcol + ldRow + i * 64) * K + ldCol);
        }
#pragma unroll
        for (int i = 0; i < 2; i++) {
            int row = ldRow + i * 64;
            As[0][ldCol + 0][row] = to_tf32(pa[i].x); As[0][ldCol + 1][row] = to_tf32(pa[i].y);
            As[0][ldCol + 2][row] = to_tf32(pa[i].z); As[0][ldCol + 3][row] = to_tf32(pa[i].w);
            Ws[0][ldCol + 0][row] = to_tf32(pw[i].x); Ws[0][ldCol + 1][row] = to_tf32(pw[i].y);
            Ws[0][ldCol + 2][row] = to_tf32(pw[i].z); Ws[0][ldCol + 3][row] = to_tf32(pw[i].w);
        }
    }
    __syncthreads();

    float acc[4][4][4];
#pragma unroll
    for (int mt = 0; mt < 4; mt++)
#pragma unroll
        for (int nt = 0; nt < 4; nt++)
#pragma unroll
            for (int r = 0; r < 4; r++) acc[mt][nt][r] = 0.f;

    const int nk = K / BKK;
    for (int t = 0; t < nk; t++) {
        const int cur = t & 1;
        if (t + 1 < nk) {
            const int kt = (t + 1) * BKK;
#pragma unroll
            for (int i = 0; i < 2; i++) {
                int gr = brow + ldRow + i * 64;
                pa[i] = (gr < M) ? *reinterpret_cast<const float4*>(A + (size_t)gr * K + kt + ldCol)
                                 : make_float4(0.f, 0.f, 0.f, 0.f);
                pw[i] = *reinterpret_cast<const float4*>(W + (size_t)(bcol + ldRow + i * 64) * K + kt + ldCol);
            }
        }

#pragma unroll
        for (int ks = 0; ks < 2; ks++) {
            const int kb = ks * 8;
            uint32_t af[4][4], bf[4][2];
#pragma unroll
            for (int mt = 0; mt < 4; mt++) {
                const int m0 = wm + mt * 16;
                af[mt][0] = __float_as_uint(As[cur][kb + lc    ][m0 + lr    ]);
                af[mt][1] = __float_as_uint(As[cur][kb + lc    ][m0 + lr + 8]);
                af[mt][2] = __float_as_uint(As[cur][kb + lc + 4][m0 + lr    ]);
                af[mt][3] = __float_as_uint(As[cur][kb + lc + 4][m0 + lr + 8]);
            }
#pragma unroll
            for (int nt = 0; nt < 4; nt++) {
                const int n0 = wn + nt * 8;
                bf[nt][0] = __float_as_uint(Ws[cur][kb + lc    ][n0 + lr]);
                bf[nt][1] = __float_as_uint(Ws[cur][kb + lc + 4][n0 + lr]);
            }
#pragma unroll
            for (int mt = 0; mt < 4; mt++)
#pragma unroll
                for (int nt = 0; nt < 4; nt++)
                    mma_tf32(acc[mt][nt], af[mt], bf[nt]);
        }

        if (t + 1 < nk) {
            const int nxt = cur ^ 1;
#pragma unroll
            for (int i = 0; i < 2; i++) {
                int row = ldRow + i * 64;
                As[nxt][ldCol + 0][row] = to_tf32(pa[i].x); As[nxt][ldCol + 1][row] = to_tf32(pa[i].y);
                As[nxt][ldCol + 2][row] = to_tf32(pa[i].z); As[nxt][ldCol + 3][row] = to_tf32(pa[i].w);
                Ws[nxt][ldCol + 0][row] = to_tf32(pw[i].x); Ws[nxt][ldCol + 1][row] = to_tf32(pw[i].y);
                Ws[nxt][ldCol + 2][row] = to_tf32(pw[i].z); Ws[nxt][ldCol + 3][row] = to_tf32(pw[i].w);
            }
        }
        __syncthreads();
    }

    // Epilogue: each mma tile stores rows {lr, lr+8}, cols {2*lc, 2*lc+1}
#pragma unroll
    for (int mt = 0; mt < 4; mt++) {
#pragma unroll
        for (int nt = 0; nt < 4; nt++) {
            const int c0 = bcol + wn + nt * 8 + lc * 2;
            const float b0 = __ldg(bias + c0);
            const float b1 = __ldg(bias + c0 + 1);
#pragma unroll
            for (int rr = 0; rr < 2; rr++) {
                const int r = brow + wm + mt * 16 + lr + rr * 8;
                if (r >= M) continue;
                const float v0 = acc[mt][nt][rr * 2 + 0] + b0;
                const float v1 = acc[mt][nt][rr * 2 + 1] + b1;
                if (EPI == 0) {
                    *reinterpret_cast<float2*>(C + (size_t)r * N + c0) = make_float2(v0, v1);
                } else {
                    const int nb = r / Lv, l = r - nb * Lv;
                    const int h = c0 >> 5, dh = c0 & 31;  // c0 even, c0+1 same head
                    float* p = C + ((((size_t)(nb * NH + h)) * Lv) + l) * DHEAD + dh;
                    p[0] = v0; p[1] = v1;
                }
            }
        }
    }
}

// ---------------------------------------------------------------------------
// Sampling + softmax, two-phase (unchanged from round 2: at L1 wavefront floor)
// ---------------------------------------------------------------------------
__global__ __launch_bounds__(256)
void msda_sample(const float* __restrict__ ref,
                 const int* __restrict__ shapes,
                 const int* __restrict__ lstart,
                 int Lq, int total)
{
    __shared__ int   s_idx[16][16][4];
    __shared__ float s_w  [16][16][4];
    __shared__ int   s_vbase[16];

    const int tid = threadIdx.x;

    // ---------------- Phase 1 ----------------
    {
        const int u  = tid >> 4;
        const int pt = tid & 15;
        const int gu = blockIdx.x * 16 + u;
        const bool act = gu < total;

        const int h  = gu & (NH - 1);
        const int mq = gu >> 3;                    // n*Lq + q

        float logit = act ? __ldg(g_attn + (size_t)gu * 16 + pt) : 0.f;
        float mx = logit;
#pragma unroll
        for (int s = 8; s > 0; s >>= 1) mx = fmaxf(mx, __shfl_xor_sync(0xffffffffu, mx, s));
        float e = __expf(logit - mx);
        float sum = e;
#pragma unroll
        for (int s = 8; s > 0; s >>= 1) sum += __shfl_xor_sync(0xffffffffu, sum, s);
        const float aw = e / sum;

        if (act) {
            const int lvl = pt >> 2;
            const int Hl = __ldg(shapes + lvl * 2 + 0);
            const int Wl = __ldg(shapes + lvl * 2 + 1);
            const int st = __ldg(lstart + lvl);

            const float rx = __ldg(ref + (size_t)mq * (NL * 2) + lvl * 2 + 0);
            const float ry = __ldg(ref + (size_t)mq * (NL * 2) + lvl * 2 + 1);
            const float ox = __ldg(g_off + (size_t)gu * 32 + 2 * pt + 0);
            const float oy = __ldg(g_off + (size_t)gu * 32 + 2 * pt + 1);

            const float x = fmaf(rx, (float)Wl, ox) - 0.5f;
            const float y = fmaf(ry, (float)Hl, oy) - 0.5f;
            const float xf = floorf(x), yf = floorf(y);
            const float lx = x - xf, ly = y - yf;
            const int x0 = (int)xf, y0 = (int)yf;
            const int x1 = x0 + 1,  y1 = y0 + 1;

            const float vx0 = (x0 >= 0 && x0 < Wl) ? 1.f : 0.f;
            const float vx1 = (x1 >= 0 && x1 < Wl) ? 1.f : 0.f;
            const float vy0 = (y0 >= 0 && y0 < Hl) ? 1.f : 0.f;
            const float vy1 = (y1 >= 0 && y1 < Hl) ? 1.f : 0.f;

            const int x0c = min(max(x0, 0), Wl - 1);
            const int x1c = min(max(x1, 0), Wl - 1);
            const int y0c = min(max(y0, 0), Hl - 1);
            const int y1c = min(max(y1, 0), Hl - 1);

            const int r0 = (st + y0c * Wl) * DHEAD;
            const int r1 = (st + y1c * Wl) * DHEAD;
            s_idx[u][pt][0] = r0 + x0c * DHEAD;
            s_idx[u][pt][1] = r0 + x1c * DHEAD;
            s_idx[u][pt][2] = r1 + x0c * DHEAD;
            s_idx[u][pt][3] = r1 + x1c * DHEAD;

            s_w[u][pt][0] = aw * (1.f - lx) * (1.f - ly) * vx0 * vy0;
            s_w[u][pt][1] = aw * lx * (1.f - ly) * vx1 * vy0;
            s_w[u][pt][2] = aw * (1.f - lx) * ly * vx0 * vy1;
            s_w[u][pt][3] = aw * lx * ly * vx1 * vy1;

            if (pt == 0) {
                const int n = mq / Lq;
                s_vbase[u] = ((n * NH + h) * Lq) * DHEAD;
            }
        }
    }
    __syncthreads();

    // ---------------- Phase 2 ----------------
    {
        const int warp = tid >> 5;
        const int lane = tid & 31;
#pragma unroll
        for (int uu = 0; uu < 2; uu++) {
            const int u  = warp * 2 + uu;
            const int gu = blockIdx.x * 16 + u;
            if (gu >= total) continue;

            const float* bp = g_value + s_vbase[u] + lane;
            float acc = 0.f;
#pragma unroll
            for (int pt = 0; pt < 16; pt++) {
                const int4   id = *reinterpret_cast<const int4*>(s_idx[u][pt]);
                const float4 w  = *reinterpret_cast<const float4*>(s_w[u][pt]);
                acc = fmaf(w.x, __ldg(bp + id.x), acc);
                acc = fmaf(w.y, __ldg(bp + id.y), acc);
                acc = fmaf(w.z, __ldg(bp + id.z), acc);
                acc = fmaf(w.w, __ldg(bp + id.w), acc);
            }
            g_acc[(size_t)gu * DHEAD + lane] = acc;
        }
    }
}

// ---------------------------------------------------------------------------
// Launch
// ---------------------------------------------------------------------------
extern "C" void kernel_launch(void* const* d_in, const int* in_sizes, int n_in,
                              void* d_out, int out_size)
{
    const float* query  = (const float*)d_in[0];
    const float* refp   = (const float*)d_in[1];
    const float* xin    = (const float*)d_in[2];
    const int*   shapes = (const int*)  d_in[3];
    const int*   lstart = (const int*)  d_in[4];
    const float* W_samp = (const float*)d_in[5];
    const float* b_samp = (const float*)d_in[6];
    const float* W_attn = (const float*)d_in[7];
    const float* b_attn = (const float*)d_in[8];
    const float* W_val  = (const float*)d_in[9];
    const float* b_val  = (const float*)d_in[10];
    const float* W_out  = (const float*)d_in[11];
    const float* b_out  = (const float*)d_in[12];
    float* out = (float*)d_out;

    const int Lq = in_sizes[0] / (BATCH * D_MODEL);
    const int M  = BATCH * Lq;

    void *pv, *po, *pa, *pc;
    cudaGetSymbolAddress(&pv, g_value);
    cudaGetSymbolAddress(&po, g_off);
    cudaGetSymbolAddress(&pa, g_attn);
    cudaGetSymbolAddress(&pc, g_acc);

    dim3 blk(256);
    dim3 grid256((M + BM - 1) / BM, D_MODEL / BN);        // N = 256
    dim3 grid128((M + BM - 1) / BM, (NH * NL * NP) / BN); // N = 128

    // 1) value projection (+ layout remap to (N,H,Lv,Dh))
    tgemm_nt<1><<<grid256, blk>>>(xin, W_val, b_val, (float*)pv, M, D_MODEL, D_MODEL, Lq);
    // 2) sampling offsets
    tgemm_nt<0><<<grid256, blk>>>(query, W_samp, b_samp, (float*)po, M, D_MODEL, D_MODEL, Lq);
    // 3) attention logits
    tgemm_nt<0><<<grid128, blk>>>(query, W_attn, b_attn, (float*)pa, M, NH * NL * NP, D_MODEL, Lq);
    // 4) softmax + deformable sampling
    {
        const int total = M * NH;                 // units (n,q,h)
        const int nblk  = (total + 15) / 16;
        msda_sample<<<nblk, blk>>>(refp, shapes, lstart, Lq, total);
    }
    // 5) output projection
    tgemm_nt<0><<<grid256, blk>>>((const float*)pc, W_out, b_out, out, M, D_MODEL, D_MODEL, Lq);
}